// round 11
// baseline (speedup 1.0000x reference)
#include <cuda_runtime.h>
#include <cuda_bf16.h>

// CL4CTR loss on GB300 — fused kernel, 2 samples per warp, pipelined gathers,
// bank-conflict-free skewed tile layout, combined divisions.
//   x:   [4096, 39] int32 field indices      (d_in[0])
//   emb: [3900000, 16] float32               (d_in[1])
//   out: scalar float32
//
// 256 blocks x 256 threads (8 warps); each warp processes samples b and b+8.
// All idx LDGs then all 10 gather LDG.128s issue back-to-back; sample A is
// processed while B's loads land. Tile layout skews row k by (k>>2)*8 floats
// so the transposed STS is conflict-free ((8c+8m+r)%32 all-distinct).
// Per-4-pair divisions are combined into one __fdividef. Last block combines,
// writes the scalar, re-zeroes accumulators (zero-invariant across replays).

#define F_FIELDS 39
#define FP 40            // base row stride (floats)
#define TILE_SZ 672      // 15*40 + 3*8 + 40 rounded up
#define NWARPS 8
#define NSAMP 16         // tile slots per block (2 per warp)
#define NTHREADS 256
#define NBLOCKS 256
#define EPSV 1e-4f

// skewed row start: float offset of row k
#define ROWOFF(k) ((k) * FP + ((k) >> 2) * 8)

__device__ float g_s[624];       // s[f][d]
__device__ float g_acc[2];       // [0]=sum(sq), [1]=uniform sum
__device__ unsigned g_count;     // arrival counter (returns to 0 each run)

#define TT(i,j,w) ((unsigned)((i) | ((j)<<8) | ((w)<<16)))
__constant__ unsigned c_tiles[64] = {
  TT(0,0,1),TT(0,1,2),TT(0,2,2),TT(0,3,2),TT(0,4,2),TT(0,5,2),TT(0,6,2),TT(0,7,2),TT(0,8,2),TT(0,9,2),
  TT(1,1,1),TT(1,2,2),TT(1,3,2),TT(1,4,2),TT(1,5,2),TT(1,6,2),TT(1,7,2),TT(1,8,2),TT(1,9,2),
  TT(2,2,1),TT(2,3,2),TT(2,4,2),TT(2,5,2),TT(2,6,2),TT(2,7,2),TT(2,8,2),TT(2,9,2),
  TT(3,3,1),TT(3,4,2),TT(3,5,2),TT(3,6,2),TT(3,7,2),TT(3,8,2),TT(3,9,2),
  TT(4,4,1),TT(4,5,2),TT(4,6,2),TT(4,7,2),TT(4,8,2),TT(4,9,2),
  TT(5,5,1),TT(5,6,2),TT(5,7,2),TT(5,8,2),TT(5,9,2),
  TT(6,6,1),TT(6,7,2),TT(6,8,2),TT(6,9,2),
  TT(7,7,1),TT(7,8,2),TT(7,9,2),
  TT(8,8,1),TT(8,9,2),
  TT(9,9,1),
  TT(0,0,0),TT(0,0,0),TT(0,0,0),TT(0,0,0),TT(0,0,0),TT(0,0,0),TT(0,0,0),TT(0,0,0),TT(0,0,0)
};

typedef unsigned long long ull;

__device__ __forceinline__ ull pk2(float x) {            // (x, x) packed
    ull r; asm("mov.b64 %0, {%1, %1};" : "=l"(r) : "f"(x)); return r;
}
__device__ __forceinline__ void upk(ull v, float& x, float& y) {
    asm("mov.b64 {%0, %1}, %2;" : "=f"(x), "=f"(y) : "l"(v));
}
__device__ __forceinline__ ull fma2(ull a, ull b, ull c) {
    ull d; asm("fma.rn.f32x2 %0, %1, %2, %3;" : "=l"(d) : "l"(a), "l"(b), "l"(c));
    return d;
}

// norms from gather registers (quad butterfly), skewed transposed store, sum(sq)
__device__ __forceinline__ float store_norms(const float4* g, float* tile,
                                             float* nr, int lane) {
    float sumsq = 0.0f;
    #pragma unroll
    for (int it = 0; it < 5; it++) {
        int i = it * 32 + lane;
        int r = i >> 2, c = i & 3;
        float4 v = g[it];
        float sqp = fmaf(v.x, v.x, fmaf(v.y, v.y, fmaf(v.z, v.z, v.w * v.w)));
        sumsq += sqp;                                  // i>=156 chunks are zero
        float sr = sqp;
        sr += __shfl_xor_sync(0xffffffffu, sr, 1);
        sr += __shfl_xor_sync(0xffffffffu, sr, 2);
        if (i < 156) {
            if (c == 0) nr[r] = sqrtf(sr);
            // k = 4c+m, m=0..3: addr = c*168 + m*40 + r -> banks (8c+8m+r)%32
            float* dst = &tile[c * 168 + r];
            dst[0]      = v.x;
            dst[40]     = v.y;
            dst[80]     = v.z;
            dst[120]    = v.w;
        }
    }
    // zero pad row r=39 for all 16 k rows
    if (lane < 16) tile[ROWOFF(lane) + 39] = 0.0f;
    if (lane == 16) nr[39] = 0.0f;
    return sumsq;
}

// packed-fp32x2 Gram over the 55+9pad triangle tiles, combined divisions
__device__ __forceinline__ float gram_full(const float* tile, const float* nr,
                                           int lane) {
    float usum = 0.0f;
    #pragma unroll
    for (int rep = 0; rep < 2; rep++) {
        unsigned e = c_tiles[(rep << 5) + lane];
        int I = e & 255, J = (e >> 8) & 255;
        float wgt = (float)(e >> 16);

        ull acc[4][2];
        #pragma unroll
        for (int i = 0; i < 4; i++) { acc[i][0] = 0ull; acc[i][1] = 0ull; }

        #pragma unroll
        for (int k = 0; k < 16; k++) {
            const float* rowk = tile + ROWOFF(k);
            float4     av = *reinterpret_cast<const float4*>(rowk + 4 * I);
            ulonglong2 bp = *reinterpret_cast<const ulonglong2*>(rowk + 4 * J);
            ull a0 = pk2(av.x), a1 = pk2(av.y), a2 = pk2(av.z), a3 = pk2(av.w);
            acc[0][0] = fma2(a0, bp.x, acc[0][0]);  acc[0][1] = fma2(a0, bp.y, acc[0][1]);
            acc[1][0] = fma2(a1, bp.x, acc[1][0]);  acc[1][1] = fma2(a1, bp.y, acc[1][1]);
            acc[2][0] = fma2(a2, bp.x, acc[2][0]);  acc[2][1] = fma2(a2, bp.y, acc[2][1]);
            acc[3][0] = fma2(a3, bp.x, acc[3][0]);  acc[3][1] = fma2(a3, bp.y, acc[3][1]);
        }

        float nf[4], ng[4];
        #pragma unroll
        for (int i = 0; i < 4; i++) {
            nf[i] = nr[4 * I + i];
            ng[i] = nr[4 * J + i];
        }

        float ts = 0.0f;
        #pragma unroll
        for (int i = 0; i < 4; i++) {
            float d0, d1, d2, d3;
            upk(acc[i][0], d0, d1);
            upk(acc[i][1], d2, d3);
            float A0 = fmaf(nf[i], ng[0], EPSV);
            float A1 = fmaf(nf[i], ng[1], EPSV);
            float A2 = fmaf(nf[i], ng[2], EPSV);
            float A3 = fmaf(nf[i], ng[3], EPSV);
            float p01 = A0 * A1, p23 = A2 * A3;
            float n01 = fmaf(d0, A1, d1 * A0);
            float n23 = fmaf(d2, A3, d3 * A2);
            float num = fmaf(n01, p23, n23 * p01);
            ts += __fdividef(num, p01 * p23);
        }
        usum = fmaf(wgt, ts, usum);
    }
    return usum;
}

__global__ void __launch_bounds__(NTHREADS, 2)
cl4_fused(const int* __restrict__ x, const float* __restrict__ emb,
          float* __restrict__ out) {
    __shared__ __align__(16) float s_xt[NSAMP][TILE_SZ]; // skewed tile per sample
    __shared__ float s_n[NSAMP][FP];
    __shared__ float s_red[NWARPS][2];
    __shared__ unsigned s_last;
    __shared__ float s_fin[NWARPS];

    const int wid  = threadIdx.x >> 5;         // 0..7
    const int lane = threadIdx.x & 31;
    const int bA   = blockIdx.x * NSAMP + wid; // 256*16 = 4096 samples
    const int bB   = bA + NWARPS;
    const int* xrA = x + bA * F_FIELDS;
    const int* xrB = x + bB * F_FIELDS;

    // ---- all four idx LDGs up front (coalesced), field offsets folded in
    int a0 = __ldg(&xrA[lane]) + lane * 100000;
    int a1 = (lane < 7) ? __ldg(&xrA[32 + lane]) + (32 + lane) * 100000 : 0;
    int b0 = __ldg(&xrB[lane]) + lane * 100000;
    int b1 = (lane < 7) ? __ldg(&xrB[32 + lane]) + (32 + lane) * 100000 : 0;

    // ---- 10 gather LDG.128s back-to-back: one DRAM round-trip, both samples
    float4 gA[5], gB[5];
    #pragma unroll
    for (int it = 0; it < 5; it++) {
        int i = it * 32 + lane;
        int r = i >> 2, c = i & 3;
        int row = (it < 4) ? __shfl_sync(0xffffffffu, a0, r)
                           : __shfl_sync(0xffffffffu, a1, r - 32);
        gA[it] = (i < 156)
            ? *reinterpret_cast<const float4*>(emb + (size_t)row * 16 + c * 4)
            : make_float4(0.f, 0.f, 0.f, 0.f);
    }
    #pragma unroll
    for (int it = 0; it < 5; it++) {
        int i = it * 32 + lane;
        int r = i >> 2, c = i & 3;
        int row = (it < 4) ? __shfl_sync(0xffffffffu, b0, r)
                           : __shfl_sync(0xffffffffu, b1, r - 32);
        gB[it] = (i < 156)
            ? *reinterpret_cast<const float4*>(emb + (size_t)row * 16 + c * 4)
            : make_float4(0.f, 0.f, 0.f, 0.f);
    }

    float* tileA = s_xt[wid];
    float* tileB = s_xt[wid + NWARPS];

    // ---- process A while B's gathers are still in flight
    float sumsq = store_norms(gA, tileA, s_n[wid], lane);
    __syncwarp();
    float usum  = gram_full(tileA, s_n[wid], lane);

    // ---- process B (loads have long since landed)
    sumsq += store_norms(gB, tileB, s_n[wid + NWARPS], lane);
    __syncwarp();
    usum  += gram_full(tileB, s_n[wid + NWARPS], lane);

    // ---- warp reductions
    #pragma unroll
    for (int o = 16; o; o >>= 1) {
        usum  += __shfl_xor_sync(0xffffffffu, usum, o);
        sumsq += __shfl_xor_sync(0xffffffffu, sumsq, o);
    }
    if (lane == 0) { s_red[wid][0] = sumsq; s_red[wid][1] = usum; }
    __syncthreads();   // only block-wide sync in the main path

    // ---- block-level s[39][16] partial over 16 tiles + scalars -> atomics
    for (int e = threadIdx.x; e < 624; e += NTHREADS) {
        int f = e >> 4, k = e & 15;
        int off = ROWOFF(k) + f;
        float v = 0.0f;
        #pragma unroll
        for (int ss = 0; ss < NSAMP; ss++) v += s_xt[ss][off];
        atomicAdd(&g_s[e], v);
    }
    if (threadIdx.x == 0) {
        float a = 0.0f, u = 0.0f;
        #pragma unroll
        for (int ww = 0; ww < NWARPS; ww++) { a += s_red[ww][0]; u += s_red[ww][1]; }
        atomicAdd(&g_acc[0], a);
        atomicAdd(&g_acc[1], u);
    }

    // ---- last-block election
    __threadfence();
    __syncthreads();
    if (threadIdx.x == 0) s_last = atomicAdd(&g_count, 1u);
    __syncthreads();
    if (s_last != NBLOCKS - 1) return;

    // ---- final: sum(s^2), combine, write scalar, RE-ZERO accumulators
    float ssq = 0.0f;
    for (int e = threadIdx.x; e < 624; e += NTHREADS) {
        float v = g_s[e];
        ssq = fmaf(v, v, ssq);
        g_s[e] = 0.0f;                                // restore zero-invariant
    }
    #pragma unroll
    for (int o = 16; o; o >>= 1) ssq += __shfl_xor_sync(0xffffffffu, ssq, o);
    if (lane == 0) s_fin[wid] = ssq;
    __syncthreads();

    if (threadIdx.x == 0) {
        float st = 0.0f;
        #pragma unroll
        for (int ww = 0; ww < NWARPS; ww++) st += s_fin[ww];
        double sumsq_t = (double)g_acc[0];
        double usum_t  = (double)g_acc[1];
        double pair    = 4096.0 * sumsq_t - (double)st;
        double align   = pair / (8386560.0 * 39.0);        // n_pairs * F
        double uni     = usum_t / (4096.0 * 39.0 * 39.0);  // B * F * F
        out[0] = (float)((align + uni) * 0.01);            // * BETA
        g_acc[0] = 0.0f;
        g_acc[1] = 0.0f;
        g_count  = 0u;                                     // reset for next replay
    }
}

extern "C" void kernel_launch(void* const* d_in, const int* in_sizes, int n_in,
                              void* d_out, int out_size) {
    const int*   x   = (const int*)d_in[0];
    const float* emb = (const float*)d_in[1];
    cl4_fused<<<NBLOCKS, NTHREADS>>>(x, emb, (float*)d_out);
}